// round 6
// baseline (speedup 1.0000x reference)
#include <cuda_runtime.h>

namespace {
constexpr int Bn = 256, Tn = 64, Mn = 256, Hn = 256, K2H = 512, G4H = 1024;
constexpr int NSX = 8;   // split-K slices for x1 (K=512, slice 64)
constexpr int NSG = 4;   // split-K slices for G1 (K=256, slice 64)
constexpr int GRID_P = 384;
}

// ---------------- device scratch (no allocations allowed) ----------------
__device__ float g_enc[Bn * Tn * Mn];       // enc (b,t,m)
__device__ float g_y1 [Bn * Tn * Mn];       // enc @ U_d^T
__device__ float g_S  [Bn * K2H];           // [d | sp] per batch row
__device__ float g_x1p[NSX * Bn * Mn];      // x1 split-K partials
__device__ float g_G1p[NSG * Bn * G4H];     // G1 split-K partials
__device__ float g_gbias[G4H];              // b_ih + b_hh
__device__ float g_wv [513];                // folded W_y/v_y projection + const

// dataflow counters (monotonic within one kernel_launch; reset by k_pre)
__device__ unsigned g_x1cnt[4];             // x1 jobs done per m-group (32/step)
__device__ unsigned g_g1cnt[4];             // G1 jobs done per m-group (64/step)
__device__ unsigned g_scnt [4];             // attn/LSTM done per batch-group (64/step)

__device__ __forceinline__ float tanh_mufu(float x) {      // attention only
    float y; asm("tanh.approx.f32 %0, %1;" : "=f"(y) : "f"(x)); return y;
}
__device__ __forceinline__ float tanh_acc(float x) {       // LSTM gates
    float e = __expf(2.f * x);
    return 1.f - __fdividef(2.f, e + 1.f);
}
__device__ __forceinline__ float sigm(float x) {
    return __fdividef(1.f, 1.f + __expf(-x));
}
__device__ __forceinline__ void wait_ge(const unsigned* p, unsigned tgt) {
    while (*(volatile const unsigned*)p < tgt) __nanosleep(32);
}

// ---------------- prep: transpose enc, zero state/counters, fold bias ----
__global__ void k_pre(const float* __restrict__ enc_in,
                      const float* __restrict__ b_ih,
                      const float* __restrict__ b_hh) {
    int idx = blockIdx.x * blockDim.x + threadIdx.x;
    int stride = gridDim.x * blockDim.x;
    for (int i = idx; i < Bn * Tn * Mn; i += stride) {
        int m = i & (Mn - 1);
        int t = (i >> 8) & (Tn - 1);
        int b = i >> 14;
        g_enc[i] = enc_in[(size_t)t * Bn * Mn + (size_t)b * Mn + m];
    }
    for (int i = idx; i < Bn * K2H; i += stride) g_S[i] = 0.f;
    for (int i = idx; i < G4H; i += stride) g_gbias[i] = b_ih[i] + b_hh[i];
    if (idx < 4) { g_x1cnt[idx] = 0u; g_g1cnt[idx] = 0u; g_scnt[idx] = 0u; }
}

// ---------------- fold final projection ----------------------------------
__global__ void k_wv(const float* __restrict__ W_y, const float* __restrict__ v_y,
                     const float* __restrict__ b_Wy, const float* __restrict__ b_vy) {
    int k = threadIdx.x;  // 512 threads
    float s = 0.f;
    for (int j = 0; j < Hn; j++) s += v_y[j] * W_y[(size_t)j * K2H + k];
    g_wv[k] = s;
    if (k == 0) {
        float s0 = 0.f;
        for (int j = 0; j < Hn; j++) s0 += v_y[j] * b_Wy[j];
        g_wv[512] = s0 + b_vy[0];
    }
}

// ---- GEMM core: C[m0..+64, n0..+64] = A[.,kb..kb+ksl] * W[.,kb..kb+ksl]^T
// 128 threads, 8x4 per-thread register tile, double-buffered SMEM (BK=16).
__device__ __forceinline__ void gemm64x64(
    const float* __restrict__ A, int lda,
    const float* __restrict__ W, int ldw,
    float* __restrict__ C, int ldc,
    int m0, int n0, int kb, int ksl) {

    __shared__ __align__(16) float As[2][16 * 64];   // k-major: As[k][row]
    __shared__ __align__(16) float Ws[2][16 * 64];   // k-major: Ws[k][col]

    const int tid = threadIdx.x;
    const int tm = tid >> 4;              // 0..7  -> rows 8*tm
    const int tn = tid & 15;              // 0..15 -> cols 4*tn
    const int lr = tid >> 1;              // 0..63 loader row/col
    const int lc = (tid & 1) << 3;        // {0,8} loader k offset

    const float* Aptr = A + (size_t)(m0 + lr) * lda + kb + lc;
    const float* Wptr = W + (size_t)(n0 + lr) * ldw + kb + lc;

    float acc[8][4];
#pragma unroll
    for (int i = 0; i < 8; i++)
#pragma unroll
        for (int j = 0; j < 4; j++) acc[i][j] = 0.f;

    const int ns = ksl >> 4;
    float4 ra0 = *(const float4*)(Aptr);
    float4 ra1 = *(const float4*)(Aptr + 4);
    float4 rw0 = *(const float4*)(Wptr);
    float4 rw1 = *(const float4*)(Wptr + 4);

    {   // deposit stage 0
        float* a = As[0]; float* w = Ws[0];
        a[(lc + 0) * 64 + lr] = ra0.x; a[(lc + 1) * 64 + lr] = ra0.y;
        a[(lc + 2) * 64 + lr] = ra0.z; a[(lc + 3) * 64 + lr] = ra0.w;
        a[(lc + 4) * 64 + lr] = ra1.x; a[(lc + 5) * 64 + lr] = ra1.y;
        a[(lc + 6) * 64 + lr] = ra1.z; a[(lc + 7) * 64 + lr] = ra1.w;
        w[(lc + 0) * 64 + lr] = rw0.x; w[(lc + 1) * 64 + lr] = rw0.y;
        w[(lc + 2) * 64 + lr] = rw0.z; w[(lc + 3) * 64 + lr] = rw0.w;
        w[(lc + 4) * 64 + lr] = rw1.x; w[(lc + 5) * 64 + lr] = rw1.y;
        w[(lc + 6) * 64 + lr] = rw1.z; w[(lc + 7) * 64 + lr] = rw1.w;
    }
    __syncthreads();

    for (int s = 0; s < ns; s++) {
        const int cur = s & 1;
        if (s + 1 < ns) {                 // issue next stage's LDG early
            ra0 = *(const float4*)(Aptr + (s + 1) * 16);
            ra1 = *(const float4*)(Aptr + (s + 1) * 16 + 4);
            rw0 = *(const float4*)(Wptr + (s + 1) * 16);
            rw1 = *(const float4*)(Wptr + (s + 1) * 16 + 4);
        }
        const float* a = As[cur];
        const float* w = Ws[cur];
#pragma unroll
        for (int k = 0; k < 16; k++) {
            float4 a0 = *(const float4*)(a + k * 64 + 8 * tm);
            float4 a1 = *(const float4*)(a + k * 64 + 8 * tm + 4);
            float4 w0 = *(const float4*)(w + k * 64 + 4 * tn);
            acc[0][0] += a0.x * w0.x; acc[0][1] += a0.x * w0.y;
            acc[0][2] += a0.x * w0.z; acc[0][3] += a0.x * w0.w;
            acc[1][0] += a0.y * w0.x; acc[1][1] += a0.y * w0.y;
            acc[1][2] += a0.y * w0.z; acc[1][3] += a0.y * w0.w;
            acc[2][0] += a0.z * w0.x; acc[2][1] += a0.z * w0.y;
            acc[2][2] += a0.z * w0.z; acc[2][3] += a0.z * w0.w;
            acc[3][0] += a0.w * w0.x; acc[3][1] += a0.w * w0.y;
            acc[3][2] += a0.w * w0.z; acc[3][3] += a0.w * w0.w;
            acc[4][0] += a1.x * w0.x; acc[4][1] += a1.x * w0.y;
            acc[4][2] += a1.x * w0.z; acc[4][3] += a1.x * w0.w;
            acc[5][0] += a1.y * w0.x; acc[5][1] += a1.y * w0.y;
            acc[5][2] += a1.y * w0.z; acc[5][3] += a1.y * w0.w;
            acc[6][0] += a1.z * w0.x; acc[6][1] += a1.z * w0.y;
            acc[6][2] += a1.z * w0.z; acc[6][3] += a1.z * w0.w;
            acc[7][0] += a1.w * w0.x; acc[7][1] += a1.w * w0.y;
            acc[7][2] += a1.w * w0.z; acc[7][3] += a1.w * w0.w;
        }
        if (s + 1 < ns) {
            float* an = As[cur ^ 1]; float* wn = Ws[cur ^ 1];
            an[(lc + 0) * 64 + lr] = ra0.x; an[(lc + 1) * 64 + lr] = ra0.y;
            an[(lc + 2) * 64 + lr] = ra0.z; an[(lc + 3) * 64 + lr] = ra0.w;
            an[(lc + 4) * 64 + lr] = ra1.x; an[(lc + 5) * 64 + lr] = ra1.y;
            an[(lc + 6) * 64 + lr] = ra1.z; an[(lc + 7) * 64 + lr] = ra1.w;
            wn[(lc + 0) * 64 + lr] = rw0.x; wn[(lc + 1) * 64 + lr] = rw0.y;
            wn[(lc + 2) * 64 + lr] = rw0.z; wn[(lc + 3) * 64 + lr] = rw0.w;
            wn[(lc + 4) * 64 + lr] = rw1.x; wn[(lc + 5) * 64 + lr] = rw1.y;
            wn[(lc + 6) * 64 + lr] = rw1.z; wn[(lc + 7) * 64 + lr] = rw1.w;
            __syncthreads();
        }
    }

#pragma unroll
    for (int i = 0; i < 8; i++) {
        float4 cv; cv.x = acc[i][0]; cv.y = acc[i][1];
        cv.z = acc[i][2]; cv.w = acc[i][3];
        *(float4*)(C + (size_t)(m0 + 8 * tm + i) * ldc + n0 + 4 * tn) = cv;
    }
}

// ---------------- one-time y1 GEMM -----------------------------------------
__global__ void __launch_bounds__(128) k_y1(const float* __restrict__ U_d) {
    int id = blockIdx.x;                 // 1024 blocks
    int m0 = (id >> 2) * 64;
    int n0 = (id & 3) * 64;
    gemm64x64(g_enc, Mn, U_d, Mn, g_y1, Mn, m0, n0, 0, Mn);
}

// ---------------- attention + LSTM body (128 threads, one batch b) --------
__device__ __forceinline__ void attn_body(
        int b, int t_step,
        const float* __restrict__ y_in, const float* __restrict__ v_d,
        const float* __restrict__ w_til, const float* __restrict__ b_wt,
        const float* __restrict__ W_ih, const float* __restrict__ b_Wd,
        float* __restrict__ out) {
    const int tid = threadIdx.x;
    const int warp = tid >> 5, lane = tid & 31;
    __shared__ float sx[Mn], sv[Mn], sl[Tn], sred[4];
    __shared__ float s_ytil;

#pragma unroll
    for (int e = 0; e < 2; e++) {
        int m = tid + e * 128;
        int o = b * Mn + m;
        float v = b_Wd[m];
#pragma unroll
        for (int s = 0; s < NSX; s++) v += g_x1p[s * (Bn * Mn) + o];
        sx[m] = v;
        sv[m] = v_d[m];
    }
    __syncthreads();

    const float* y1b = g_y1 + (size_t)b * Tn * Mn;
#pragma unroll
    for (int i = 0; i < 16; i++) {
        int t = warp * 16 + i;
        const float* row = y1b + t * Mn;
        float acc = 0.f;
#pragma unroll
        for (int j = 0; j < 8; j++) {
            int m = lane + 32 * j;
            acc += tanh_mufu(sx[m] + row[m]) * sv[m];
        }
#pragma unroll
        for (int o = 16; o > 0; o >>= 1) acc += __shfl_xor_sync(0xffffffffu, acc, o);
        if (lane == 0) sl[t] = acc;
    }
    __syncthreads();

    if (warp == 0) {   // softmax over 64
        float v0 = sl[lane], v1 = sl[lane + 32];
        float mx = fmaxf(v0, v1);
#pragma unroll
        for (int o = 16; o > 0; o >>= 1) mx = fmaxf(mx, __shfl_xor_sync(0xffffffffu, mx, o));
        float e0 = __expf(v0 - mx), e1 = __expf(v1 - mx);
        float s = e0 + e1;
#pragma unroll
        for (int o = 16; o > 0; o >>= 1) s += __shfl_xor_sync(0xffffffffu, s, o);
        float inv = __fdividef(1.f, s);
        sl[lane] = e0 * inv; sl[lane + 32] = e1 * inv;
    }
    __syncthreads();

    const float* encb = g_enc + (size_t)b * Tn * Mn;
    float c0 = 0.f, c1 = 0.f;
#pragma unroll 8
    for (int t = 0; t < Tn; t++) {
        float bta = sl[t];
        c0 += bta * encb[t * Mn + tid];
        c1 += bta * encb[t * Mn + tid + 128];
    }

    float part = c0 * w_til[tid] + c1 * w_til[tid + 128];
#pragma unroll
    for (int o = 16; o > 0; o >>= 1) part += __shfl_xor_sync(0xffffffffu, part, o);
    if (lane == 0) sred[warp] = part;
    __syncthreads();
    if (tid == 0)
        s_ytil = sred[0] + sred[1] + sred[2] + sred[3]
               + w_til[Mn] * y_in[b * Tn + t_step] + b_wt[0];
    __syncthreads();
    float yt = s_ytil;

    float dnv[2];
#pragma unroll
    for (int e = 0; e < 2; e++) {
        int h = tid + e * 128;
        float gate[4];
#pragma unroll
        for (int q = 0; q < 4; q++) {
            int idx = q * Hn + h;
            float v = g_gbias[idx] + yt * W_ih[idx];
#pragma unroll
            for (int s = 0; s < NSG; s++)
                v += g_G1p[s * (Bn * G4H) + b * G4H + idx];
            gate[q] = v;
        }
        float sp = g_S[b * K2H + Hn + h];
        float spn = sigm(gate[1]) * sp + sigm(gate[0]) * tanh_acc(gate[2]);
        float dn  = sigm(gate[3]) * tanh_acc(spn);
        g_S[b * K2H + h]      = dn;
        g_S[b * K2H + Hn + h] = spn;
        dnv[e] = dn;
    }

    if (t_step == Tn - 1) {   // folded output
        float p = dnv[0] * g_wv[tid] + dnv[1] * g_wv[tid + 128]
                + c0 * g_wv[Hn + tid] + c1 * g_wv[Hn + tid + 128];
#pragma unroll
        for (int o = 16; o > 0; o >>= 1) p += __shfl_xor_sync(0xffffffffu, p, o);
        __syncthreads();
        if (lane == 0) sred[warp] = p;
        __syncthreads();
        if (tid == 0) out[b] = sred[0] + sred[1] + sred[2] + sred[3] + g_wv[512];
    }
}

// ---------------- persistent recurrence kernel ----------------------------
// 384 blocks x 128 threads, all co-resident (>=3 blocks/SM guaranteed).
// Per step: every block runs exactly one 64x64x64 GEMM job; blocks 0..255
// then run attention+LSTM for batch b=bid. Dependencies via monotonic
// per-group counters (release: fence+atomicAdd; acquire: volatile spin+fence).
__global__ void __launch_bounds__(128, 3) k_persist(
        const float* __restrict__ y_in,  const float* __restrict__ v_d,
        const float* __restrict__ w_til, const float* __restrict__ b_wt,
        const float* __restrict__ W_ih,  const float* __restrict__ b_Wd,
        const float* __restrict__ W_d,   const float* __restrict__ W_hh,
        float* __restrict__ out) {
    const int bid = blockIdx.x;
    const int tid = threadIdx.x;

    // decode this block's fixed GEMM job
    const float* jW; float* jC;
    int jldw, jldc, jm0, jn0, jkb, jgrp;
    unsigned* jcnt;
    if (bid < 128) {                      // x1: S @ W_d^T, 4m x 4n x 8 slices
        int s = bid & 7;
        jn0 = ((bid >> 3) & 3) * 64; jm0 = (bid >> 5) * 64;
        jkb = s * 64; jW = W_d; jldw = K2H;
        jC = g_x1p + s * (Bn * Mn); jldc = Mn;
        jgrp = bid >> 5; jcnt = &g_x1cnt[jgrp];
    } else {                              // G1: d @ W_hh^T, 4m x 16n x 4 slices
        int j = bid - 128;
        int s = j & 3;
        jn0 = ((j >> 2) & 15) * 64; jm0 = (j >> 6) * 64;
        jkb = s * 64; jW = W_hh; jldw = Hn;
        jC = g_G1p + s * (Bn * G4H); jldc = G4H;
        jgrp = j >> 6; jcnt = &g_g1cnt[jgrp];
    }
    const int agrp = bid >> 6;            // attn batch-group (bid < 256)

    for (int t = 0; t < Tn; t++) {
        // ---- GEMM job: needs S rows of group jgrp updated through step t-1
        if (t > 0) {
            if (tid == 0) { wait_ge(&g_scnt[jgrp], 64u * (unsigned)t); __threadfence(); }
            __syncthreads();
        }
        gemm64x64(g_S, K2H, jW, jldw, jC, jldc, jm0, jn0, jkb, 64);
        __syncthreads();
        if (tid == 0) { __threadfence(); atomicAdd(jcnt, 1u); }

        // ---- attention + LSTM for batch bid (blocks 0..255)
        if (bid < 256) {
            if (tid == 0) {
                wait_ge(&g_x1cnt[agrp], 32u * (unsigned)(t + 1));
                wait_ge(&g_g1cnt[agrp], 64u * (unsigned)(t + 1));
                __threadfence();
            }
            __syncthreads();
            attn_body(bid, t, y_in, v_d, w_til, b_wt, W_ih, b_Wd, out);
            __syncthreads();
            if (tid == 0) { __threadfence(); atomicAdd(&g_scnt[agrp], 1u); }
        }
    }
}

extern "C" void kernel_launch(void* const* d_in, const int* in_sizes, int n_in,
                              void* d_out, int out_size) {
    const float* enc  = (const float*)d_in[0];
    const float* y    = (const float*)d_in[1];
    const float* W_d  = (const float*)d_in[2];
    const float* b_Wd = (const float*)d_in[3];
    const float* U_d  = (const float*)d_in[4];
    const float* v_d  = (const float*)d_in[5];
    const float* w_t  = (const float*)d_in[6];
    const float* b_wt = (const float*)d_in[7];
    const float* W_ih = (const float*)d_in[8];
    const float* W_hh = (const float*)d_in[9];
    const float* b_ih = (const float*)d_in[10];
    const float* b_hh = (const float*)d_in[11];
    const float* W_y  = (const float*)d_in[12];
    const float* b_Wy = (const float*)d_in[13];
    const float* v_y  = (const float*)d_in[14];
    const float* b_vy = (const float*)d_in[15];

    k_pre<<<2048, 256>>>(enc, b_ih, b_hh);
    k_wv<<<1, 512>>>(W_y, v_y, b_Wy, b_vy);
    k_y1<<<1024, 128>>>(U_d);
    k_persist<<<GRID_P, 128>>>(y, v_d, w_t, b_wt, W_ih, b_Wd, W_d, W_hh,
                               (float*)d_out);
}